// round 13
// baseline (speedup 1.0000x reference)
#include <cuda_runtime.h>
#include <cuda_bf16.h>
#include <cuda_fp16.h>
#include <mma.h>
#include <cstdint>

using namespace nvcuda;

#define NB        4096
#define NBIN_PAD  4160                  // 4097 table rows padded to 64
#define HID       512
#define KEMB      256
#define NG        50
#define NELEM     100
#define NPAIR     (NELEM * NELEM)       // 10000
#define NPAIR_PAD 10048
#define HEADS     8
#define RBF_R     12.0f

// ---------------- device scratch ----------------
__device__ __align__(16) __half         g_PH[(size_t)NPAIR * HID];      // fp16 (emb@W^T + b_in)
__device__ __align__(16) uint4          g_TPa[(size_t)NB * 128];        // values {v1h x4, v2h x4}
__device__ __align__(16) uint4          g_TPb[(size_t)NB * 128];        // slopes {s1h x4, s2h x4}
__device__ __align__(16) __nv_bfloat16  g_Ah[(size_t)NPAIR_PAD * KEMB]; // emb hi
__device__ __align__(16) __nv_bfloat16  g_Al[(size_t)NPAIR_PAD * KEMB]; // emb lo
__device__ __align__(16) __nv_bfloat16  g_Bh[(size_t)KEMB * HID];       // W_in emb part hi, [k][j]
__device__ __align__(16) __nv_bfloat16  g_Bl[(size_t)KEMB * HID];       // W_in emb part lo, [k][j]
__device__ __align__(16) __nv_bfloat16  g_Rh[(size_t)NBIN_PAD * 64];    // rbf matrix hi, [b][g]
__device__ __align__(16) __nv_bfloat16  g_Rl[(size_t)NBIN_PAD * 64];    // rbf matrix lo
__device__ __align__(16) __nv_bfloat16  g_Wch[(size_t)64 * 1024];       // [Ws1||Ws2] hi, [g][j]
__device__ __align__(16) __nv_bfloat16  g_Wcl[(size_t)64 * 1024];       // [Ws1||Ws2] lo
__device__ __align__(16) float          g_Tsc[(size_t)NBIN_PAD * 1024]; // T scratch fp32
__device__ __align__(16) float4         g_WQ[1024];                     // W_out interleaved

typedef unsigned long long ull;

__device__ __forceinline__ void fma2(ull& d, ull a, ull b) {
    asm("fma.rn.f32x2 %0, %1, %2, %0;" : "+l"(d) : "l"(a), "l"(b));
}
__device__ __forceinline__ ull pack2(float x, float y) {
    ull r; asm("mov.b64 %0, {%1, %2};" : "=l"(r) : "f"(x), "f"(y)); return r;
}
__device__ __forceinline__ float2 unpack2(ull v) {
    float2 r; asm("mov.b64 {%0, %1}, %2;" : "=f"(r.x), "=f"(r.y) : "l"(v)); return r;
}
__device__ __forceinline__ float rcpa(float x) {
    float r; asm("rcp.approx.ftz.f32 %0, %1;" : "=f"(r) : "f"(x)); return r;
}

// ================= prep 0: all splits + rbf matrix + combined weights =================
#define A_UNITS   (NPAIR_PAD * 64)                 // uint2 units of emb (4 bf16 each)
#define B_UNITS   (HID * 128)                      // float2 units of W_in emb part
#define R_OFF     (A_UNITS + B_UNITS)
#define R_CNT     (NBIN_PAD * 64)
#define WC_OFF    (R_OFF + R_CNT)
#define WC_CNT    (64 * 1024)
#define WQ_OFF    (WC_OFF + WC_CNT)
#define SPLIT_TOT (WQ_OFF + 1024)
__global__ void prep_stage0(const float* __restrict__ emb_table,
                            const float* __restrict__ W_in,
                            const float* __restrict__ gate_W,
                            const float* __restrict__ W_out) {
    int idx = blockIdx.x * blockDim.x + threadIdx.x;
    if (idx < A_UNITS) {
        int pair = idx >> 6, q = idx & 63;
        float4 v = (pair < NPAIR) ? __ldg((const float4*)emb_table + (size_t)pair * 64 + q)
                                  : make_float4(0, 0, 0, 0);
        __nv_bfloat162 h01 = __floats2bfloat162_rn(v.x, v.y);
        __nv_bfloat162 h23 = __floats2bfloat162_rn(v.z, v.w);
        __nv_bfloat162 l01 = __floats2bfloat162_rn(v.x - __low2float(h01), v.y - __high2float(h01));
        __nv_bfloat162 l23 = __floats2bfloat162_rn(v.z - __low2float(h23), v.w - __high2float(h23));
        uint2 hv; hv.x = *(uint32_t*)&h01; hv.y = *(uint32_t*)&h23;
        uint2 lv; lv.x = *(uint32_t*)&l01; lv.y = *(uint32_t*)&l23;
        ((uint2*)g_Ah)[idx] = hv;
        ((uint2*)g_Al)[idx] = lv;
    } else if (idx < A_UNITS + B_UNITS) {
        int r = idx - A_UNITS;
        int j = r >> 7, q = r & 127;                 // k = 2q, 2q+1
        float2 v = *(const float2*)(W_in + (size_t)j * 306 + q * 2);
        __nv_bfloat16 h0 = __float2bfloat16(v.x);
        __nv_bfloat16 h1 = __float2bfloat16(v.y);
        g_Bh[(size_t)(q * 2)     * HID + j] = h0;
        g_Bh[(size_t)(q * 2 + 1) * HID + j] = h1;
        g_Bl[(size_t)(q * 2)     * HID + j] = __float2bfloat16(v.x - __bfloat162float(h0));
        g_Bl[(size_t)(q * 2 + 1) * HID + j] = __float2bfloat16(v.y - __bfloat162float(h1));
    } else if (idx < WC_OFF) {
        int r = idx - R_OFF;
        int b = r >> 6, g = r & 63;
        float val = 0.0f;
        if (g < NG && b <= NB) {
            const float delta = RBF_R / 49.0f;
            const float coeff = -0.5f / (delta * delta);
            const float binw  = RBF_R / (float)NB;
            float t = (float)b * binw - (float)g * delta;
            val = __expf(coeff * t * t);
        }
        __nv_bfloat16 h = __float2bfloat16(val);
        g_Rh[r] = h;
        g_Rl[r] = __float2bfloat16(val - __bfloat162float(h));
    } else if (idx < WQ_OFF) {
        int r = idx - WC_OFF;
        int k = r >> 10, j = r & 1023;
        float val = 0.0f;
        if (k < NG)
            val = (j < 512) ? W_in[(size_t)j * 306 + 256 + k]
                            : gate_W[(size_t)(j - 512) * NG + k];
        __nv_bfloat16 h = __float2bfloat16(val);
        g_Wch[r] = h;
        g_Wcl[r] = __float2bfloat16(val - __bfloat162float(h));
    } else if (idx < SPLIT_TOT) {
        int r = idx - WQ_OFF;   // [0, 1024)
        int lane = r & 31;
        int hpp  = (r >> 5) & 1;
        int jpos = (r >> 6) & 3;
        int jq   = r >> 8;
        int jj   = (jq * 32 + lane) * 4 + jpos;
        g_WQ[r] = make_float4(W_out[(4 * hpp + 0) * HID + jj],
                              W_out[(4 * hpp + 1) * HID + jj],
                              W_out[(4 * hpp + 2) * HID + jj],
                              W_out[(4 * hpp + 3) * HID + jj]);
    }
}

// ================= prep 1: combined WMMA (P GEMM + T GEMM) =================
#define PW_M   64
#define PW_N   128
#define PW_KT  32
#define A_LD   40
#define B_LD   264
#define EP_LD  132
#define PW_SMEM_BYTES (2 * (PW_M * A_LD * 2) + 2 * (PW_KT * B_LD * 2))   // 44032
#define PX_T   157     // grid.x boundary: x<157 -> P GEMM, x>=157 -> T GEMM

__global__ void __launch_bounds__(256, 3)
prep_gemms(const float* __restrict__ b_in) {
    extern __shared__ char smraw[];
    __nv_bfloat16* Ah = (__nv_bfloat16*)smraw;                 // [64][A_LD]
    __nv_bfloat16* Al = Ah + PW_M * A_LD;
    __nv_bfloat16* Bh = Al + PW_M * A_LD;                      // [32][B_LD]
    __nv_bfloat16* Bl = Bh + PW_KT * B_LD;
    float* Ep = (float*)smraw;                                 // overlay [64][EP_LD]

    const int tid = threadIdx.x;
    const int w   = tid >> 5;
    const int wm  = w >> 2;     // 0..1
    const int wn  = w & 3;      // 0..3
    const bool isT = (blockIdx.x >= PX_T);
    if (!isT && blockIdx.y >= 4) return;

    const int m0 = (isT ? (blockIdx.x - PX_T) : blockIdx.x) * PW_M;
    const int n0 = blockIdx.y * PW_N;
    const int KTOT    = isT ? 64 : KEMB;
    const int Astride = isT ? 64 : KEMB;
    const int Bstride = isT ? 1024 : HID;
    const __nv_bfloat16* srcAh = isT ? g_Rh  : g_Ah;
    const __nv_bfloat16* srcAl = isT ? g_Rl  : g_Al;
    const __nv_bfloat16* srcBh = isT ? g_Wch : g_Bh;
    const __nv_bfloat16* srcBl = isT ? g_Wcl : g_Bl;

    wmma::fragment<wmma::accumulator, 16, 16, 16, float> acc[2][2];
#pragma unroll
    for (int mi = 0; mi < 2; ++mi)
#pragma unroll
        for (int ni = 0; ni < 2; ++ni) wmma::fill_fragment(acc[mi][ni], 0.0f);

    for (int kt = 0; kt < KTOT; kt += PW_KT) {
        __syncthreads();
        // ---- stage A: 2 halves x 64 rows x 4 uint4 = 512 ----
#pragma unroll
        for (int i = tid; i < 512; i += 256) {
            int half = i >> 8;
            int r = (i & 255) >> 2, q = i & 3;
            const __nv_bfloat16* src = (half ? srcAl : srcAh) + (size_t)(m0 + r) * Astride + kt;
            __nv_bfloat16* dst = (half ? Al : Ah) + r * A_LD;
            ((uint4*)dst)[q] = ((const uint4*)src)[q];
        }
        // ---- stage B: 2 halves x 32 rows x 16 uint4 = 1024 ----
#pragma unroll
        for (int i = tid; i < 1024; i += 256) {
            int half = i >> 9;
            int r = (i & 511) >> 4, q = i & 15;
            const __nv_bfloat16* src = (half ? srcBl : srcBh) + (size_t)(kt + r) * Bstride + n0;
            __nv_bfloat16* dst = (half ? Bl : Bh) + r * B_LD;
            ((uint4*)dst)[q] = ((const uint4*)src)[q];
        }
        __syncthreads();
        // ---- MMA: 2 k-steps of 16, 3-term bf16 split ----
#pragma unroll
        for (int kk = 0; kk < 2; ++kk) {
            wmma::fragment<wmma::matrix_a, 16, 16, 16, __nv_bfloat16, wmma::row_major> ah[2], al[2];
            wmma::fragment<wmma::matrix_b, 16, 16, 16, __nv_bfloat16, wmma::row_major> bh[2], bl[2];
#pragma unroll
            for (int mi = 0; mi < 2; ++mi) {
                wmma::load_matrix_sync(ah[mi], Ah + (wm * 32 + mi * 16) * A_LD + kk * 16, A_LD);
                wmma::load_matrix_sync(al[mi], Al + (wm * 32 + mi * 16) * A_LD + kk * 16, A_LD);
            }
#pragma unroll
            for (int ni = 0; ni < 2; ++ni) {
                wmma::load_matrix_sync(bh[ni], Bh + (kk * 16) * B_LD + wn * 32 + ni * 16, B_LD);
                wmma::load_matrix_sync(bl[ni], Bl + (kk * 16) * B_LD + wn * 32 + ni * 16, B_LD);
            }
#pragma unroll
            for (int mi = 0; mi < 2; ++mi)
#pragma unroll
                for (int ni = 0; ni < 2; ++ni) {
                    wmma::mma_sync(acc[mi][ni], ah[mi], bh[ni], acc[mi][ni]);
                    wmma::mma_sync(acc[mi][ni], ah[mi], bl[ni], acc[mi][ni]);
                    wmma::mma_sync(acc[mi][ni], al[mi], bh[ni], acc[mi][ni]);
                }
        }
    }
    __syncthreads();   // stage buffers dead; overlay epilogue
#pragma unroll
    for (int mi = 0; mi < 2; ++mi)
#pragma unroll
        for (int ni = 0; ni < 2; ++ni)
            wmma::store_matrix_sync(Ep + (wm * 32 + mi * 16) * EP_LD + wn * 32 + ni * 16,
                                    acc[mi][ni], EP_LD, wmma::mem_row_major);
    __syncthreads();
    if (isT) {
#pragma unroll
        for (int i = tid; i < PW_M * PW_N; i += 256) {
            int r = i >> 7, c = i & 127;
            g_Tsc[(size_t)(m0 + r) * 1024 + n0 + c] = Ep[r * EP_LD + c];
        }
    } else {
#pragma unroll
        for (int i = tid; i < PW_M * PW_N; i += 256) {
            int r = i >> 7, c = i & 127;
            int pair = m0 + r;
            if (pair < NPAIR)
                g_PH[(size_t)pair * HID + n0 + c] =
                    __float2half(Ep[r * EP_LD + c] + __ldg(&b_in[n0 + c]));
        }
    }
}

// ================= prep 2: pack values + slopes from T scratch =================
__global__ void prep_pack() {
    int idx = blockIdx.x * blockDim.x + threadIdx.x;   // NB * 128
    if (idx >= NB * 128) return;
    int b = idx >> 7, gi = idx & 127;
    int q = gi * 4;
    const float* row  = g_Tsc + (size_t)b * 1024;
    const float* rown = row + 1024;
    float4 c1 = *(const float4*)(row  + q);
    float4 c2 = *(const float4*)(row  + 512 + q);
    float4 n1 = *(const float4*)(rown + q);
    float4 n2 = *(const float4*)(rown + 512 + q);
    uint4 A, B; __half2 h;
    h = __floats2half2_rn(c1.x, c1.y); A.x = *(uint32_t*)&h;
    h = __floats2half2_rn(c1.z, c1.w); A.y = *(uint32_t*)&h;
    h = __floats2half2_rn(c2.x, c2.y); A.z = *(uint32_t*)&h;
    h = __floats2half2_rn(c2.z, c2.w); A.w = *(uint32_t*)&h;
    h = __floats2half2_rn(n1.x - c1.x, n1.y - c1.y); B.x = *(uint32_t*)&h;
    h = __floats2half2_rn(n1.z - c1.z, n1.w - c1.w); B.y = *(uint32_t*)&h;
    h = __floats2half2_rn(n2.x - c2.x, n2.y - c2.y); B.z = *(uint32_t*)&h;
    h = __floats2half2_rn(n2.z - c2.z, n2.w - c2.w); B.w = *(uint32_t*)&h;
    g_TPa[idx] = A;
    g_TPb[idx] = B;
}

// ================= main kernel: 2-edge groups for occ=3 =================
#define MT          256
#define BEDG        64
#define WQS_F       4096
#define RB_F        (8 * 32 * 33)
#define STG_F       (WQS_F + RB_F)
#define MAIN_SMEM_B ((STG_F + 192) * 4)

__global__ void __launch_bounds__(MT, 3)
pair_main(const int* __restrict__ anum,
          const int* __restrict__ edge_index,
          const int* __restrict__ edge_to_src,
          const float* __restrict__ dist,
          const float* __restrict__ b_out,
          float* __restrict__ out, int E) {
    extern __shared__ float sm[];
    float4* Wq4  = (float4*)sm;
    float* Rb    = sm + WQS_F;
    int*   spidx = (int*)(sm + STG_F);
    int*   sbin  = (int*)(sm + STG_F + 64);
    float* sfrac = sm + STG_F + 128;

    const int tid  = threadIdx.x;
    const int wid  = tid >> 5;
    const int lane = tid & 31;
    const int e0   = blockIdx.x * BEDG;

    for (int i = tid; i < 1024; i += MT)
        Wq4[i] = g_WQ[i];
    if (tid < BEDG) {
        int e = e0 + tid; if (e >= E) e = E - 1;
        int f = edge_to_src[e];
        int i0 = edge_index[f];
        int i1 = edge_index[E + f];
        spidx[tid] = anum[i0] + NELEM * anum[i1];
        float x = dist[e] * ((float)NB / RBF_R);
        int b = (int)x; if (b > NB - 1) b = NB - 1;
        sbin[tid] = b;
        sfrac[tid] = x - (float)b;
    }
    __syncthreads();

    const uint2* P2 = (const uint2*)g_PH;
    float* RbW = Rb + wid * (32 * 33);
    float bo8 = __ldg(&b_out[lane & 7]);

#pragma unroll 1
    for (int grp = 0; grp < 4; ++grp) {
        int pe[2], be[2]; __half2 fh2[2];
#pragma unroll
        for (int e = 0; e < 2; ++e) {
            int sl = wid * 8 + grp * 2 + e;
            pe[e] = spidx[sl]; be[e] = sbin[sl];
            fh2[e] = __float2half2_rn(sfrac[sl]);
        }
        ull po2[2][4];
#pragma unroll
        for (int a = 0; a < 2; a++)
#pragma unroll
            for (int b = 0; b < 4; b++) po2[a][b] = 0ull;

#pragma unroll
        for (int jq = 0; jq < 4; ++jq) {
            const int off = jq * 32 + lane;
            // ---- batched load front: 6 independent LDGs ----
            uint4 tA[2], tB[2]; uint2 ph[2];
#pragma unroll
            for (int e = 0; e < 2; ++e) {
                size_t tr = (size_t)be[e] * 128 + off;
                tA[e] = __ldg(g_TPa + tr);
                tB[e] = __ldg(g_TPb + tr);
                ph[e] = __ldg(P2 + (size_t)pe[e] * 128 + off);
            }
            ull h[2][4];
#pragma unroll
            for (int e = 0; e < 2; ++e) {
                __half2 f2 = fh2[e];
                __half2 t1a = __hfma2(f2, *(const __half2*)&tB[e].x, *(const __half2*)&tA[e].x);
                __half2 t1b = __hfma2(f2, *(const __half2*)&tB[e].y, *(const __half2*)&tA[e].y);
                __half2 g2a = __hfma2(f2, *(const __half2*)&tB[e].z, *(const __half2*)&tA[e].z);
                __half2 g2b = __hfma2(f2, *(const __half2*)&tB[e].w, *(const __half2*)&tA[e].w);
                __half2 pa  = __hadd2(*(const __half2*)&ph[e].x, t1a);
                __half2 pb  = __hadd2(*(const __half2*)&ph[e].y, t1b);
                float2 p01 = __half22float2(pa);
                float2 p23 = __half22float2(pb);
                float2 g01 = __half22float2(g2a);
                float2 g23 = __half22float2(g2b);
                float q0 = 1.0f + __expf(-p01.x);
                float q1 = 1.0f + __expf(-p01.y);
                float q2 = 1.0f + __expf(-p23.x);
                float q3 = 1.0f + __expf(-p23.y);
                float q01 = q0 * q1, q23 = q2 * q3;
                float rall = rcpa(q01 * q23);
                float r01 = rall * q23, r23 = rall * q01;
                float hv0 = p01.x * g01.x * (r01 * q1);
                float hv1 = p01.y * g01.y * (r01 * q0);
                float hv2 = p23.x * g23.x * (r23 * q3);
                float hv3 = p23.y * g23.y * (r23 * q2);
                h[e][0] = pack2(hv0, hv0); h[e][1] = pack2(hv1, hv1);
                h[e][2] = pack2(hv2, hv2); h[e][3] = pack2(hv3, hv3);
            }
#pragma unroll
            for (int jpos = 0; jpos < 4; ++jpos) {
#pragma unroll
                for (int hpp = 0; hpp < 2; ++hpp) {
                    float4 wv = Wq4[((jq * 4 + jpos) * 2 + hpp) * 32 + lane];
                    ull w01 = ((const ull*)&wv)[0];
                    ull w23 = ((const ull*)&wv)[1];
#pragma unroll
                    for (int e = 0; e < 2; ++e) {
                        fma2(po2[e][2 * hpp],     w01, h[e][jpos]);
                        fma2(po2[e][2 * hpp + 1], w23, h[e][jpos]);
                    }
                }
            }
        }

        // per-warp smem reduction (2 edges -> lanes 0..15)
#pragma unroll
        for (int e2 = 0; e2 < 2; ++e2)
#pragma unroll
            for (int hp = 0; hp < 4; ++hp) {
                float2 v = unpack2(po2[e2][hp]);
                RbW[lane * 33 + e2 * 8 + 2 * hp]     = v.x;
                RbW[lane * 33 + e2 * 8 + 2 * hp + 1] = v.y;
            }
        __syncwarp();
        if (lane < 16) {
            float s = bo8;
#pragma unroll
            for (int l = 0; l < 32; ++l) s += RbW[l * 33 + lane];
            int e2 = lane >> 3, hh = lane & 7;
            int ge = e0 + wid * 8 + grp * 2 + e2;
            if (ge < E) out[(size_t)hh * E + ge] = s;
        }
        __syncwarp();
    }
}

// ================= launch =================
extern "C" void kernel_launch(void* const* d_in, const int* in_sizes, int n_in,
                              void* d_out, int out_size) {
    const int*   anum        = (const int*)d_in[0];
    const int*   edge_index  = (const int*)d_in[1];
    const int*   edge_to_src = (const int*)d_in[2];
    const float* dist        = (const float*)d_in[3];
    const float* emb_table   = (const float*)d_in[4];
    const float* gate_W      = (const float*)d_in[5];
    const float* W_in        = (const float*)d_in[6];
    const float* b_in        = (const float*)d_in[7];
    const float* W_out       = (const float*)d_in[8];
    const float* b_out       = (const float*)d_in[9];
    float* out = (float*)d_out;
    const int E = in_sizes[2];

    prep_stage0<<<(SPLIT_TOT + 255) / 256, 256>>>(emb_table, W_in, gate_W, W_out);

    {
        dim3 grid(PX_T + NBIN_PAD / PW_M, 8);   // (157+65, 8)
        cudaFuncSetAttribute(prep_gemms, cudaFuncAttributeMaxDynamicSharedMemorySize, PW_SMEM_BYTES);
        prep_gemms<<<grid, 256, PW_SMEM_BYTES>>>(b_in);
    }

    prep_pack<<<(NB * 128 + 255) / 256, 256>>>();

    cudaFuncSetAttribute(pair_main, cudaFuncAttributeMaxDynamicSharedMemorySize, MAIN_SMEM_B);
    pair_main<<<(E + BEDG - 1) / BEDG, MT, MAIN_SMEM_B>>>(
        anum, edge_index, edge_to_src, dist, b_out, out, E);
}

// round 14
// speedup vs baseline: 1.0703x; 1.0703x over previous
#include <cuda_runtime.h>
#include <cuda_bf16.h>
#include <cuda_fp16.h>
#include <mma.h>
#include <cstdint>

using namespace nvcuda;

#define NB        4096
#define NBIN_PAD  4160
#define HID       512
#define KEMB      256
#define NG        50
#define NELEM     100
#define NPAIR     (NELEM * NELEM)       // 10000
#define NPAIR_PAD 10048
#define HEADS     8
#define RBF_R     12.0f

// ---------------- device scratch ----------------
__device__ __align__(16) __half         g_PH[(size_t)NPAIR * HID];      // fp16 (emb@W^T + b_in)
__device__ __align__(16) uint4          g_TPa[(size_t)NB * 128];        // values {v1h x4, v2h x4}
__device__ __align__(16) uint4          g_TPb[(size_t)NB * 128];        // slopes {s1h x4, s2h x4}
__device__ __align__(16) __nv_bfloat16  g_Ah[(size_t)NPAIR_PAD * KEMB]; // emb hi
__device__ __align__(16) __nv_bfloat16  g_Al[(size_t)NPAIR_PAD * KEMB]; // emb lo
__device__ __align__(16) __nv_bfloat16  g_Bh[(size_t)KEMB * HID];       // W_in emb part hi, [k][j]
__device__ __align__(16) __nv_bfloat16  g_Bl[(size_t)KEMB * HID];       // W_in emb part lo, [k][j]
__device__ __align__(16) __nv_bfloat16  g_Rh[(size_t)NBIN_PAD * 64];    // rbf matrix hi, [b][g]
__device__ __align__(16) __nv_bfloat16  g_Rl[(size_t)NBIN_PAD * 64];    // rbf matrix lo
__device__ __align__(16) __nv_bfloat16  g_Wch[(size_t)64 * 1024];       // [Ws1||Ws2] hi, [g][j]
__device__ __align__(16) __nv_bfloat16  g_Wcl[(size_t)64 * 1024];       // [Ws1||Ws2] lo
__device__ __align__(16) float4         g_WQ[1024];                     // W_out interleaved

typedef unsigned long long ull;

__device__ __forceinline__ void fma2(ull& d, ull a, ull b) {
    asm("fma.rn.f32x2 %0, %1, %2, %0;" : "+l"(d) : "l"(a), "l"(b));
}
__device__ __forceinline__ ull pack2(float x, float y) {
    ull r; asm("mov.b64 %0, {%1, %2};" : "=l"(r) : "f"(x), "f"(y)); return r;
}
__device__ __forceinline__ float2 unpack2(ull v) {
    float2 r; asm("mov.b64 {%0, %1}, %2;" : "=f"(r.x), "=f"(r.y) : "l"(v)); return r;
}
__device__ __forceinline__ float rcpa(float x) {
    float r; asm("rcp.approx.ftz.f32 %0, %1;" : "=f"(r) : "f"(x)); return r;
}

// ================= prep 0: all splits + rbf matrix + combined weights =================
#define A_UNITS   (NPAIR_PAD * 64)
#define B_UNITS   (HID * 128)
#define R_OFF     (A_UNITS + B_UNITS)
#define R_CNT     (NBIN_PAD * 64)
#define WC_OFF    (R_OFF + R_CNT)
#define WC_CNT    (64 * 1024)
#define WQ_OFF    (WC_OFF + WC_CNT)
#define SPLIT_TOT (WQ_OFF + 1024)
__global__ void prep_stage0(const float* __restrict__ emb_table,
                            const float* __restrict__ W_in,
                            const float* __restrict__ gate_W,
                            const float* __restrict__ W_out) {
    int idx = blockIdx.x * blockDim.x + threadIdx.x;
    if (idx < A_UNITS) {
        int pair = idx >> 6, q = idx & 63;
        float4 v = (pair < NPAIR) ? __ldg((const float4*)emb_table + (size_t)pair * 64 + q)
                                  : make_float4(0, 0, 0, 0);
        __nv_bfloat162 h01 = __floats2bfloat162_rn(v.x, v.y);
        __nv_bfloat162 h23 = __floats2bfloat162_rn(v.z, v.w);
        __nv_bfloat162 l01 = __floats2bfloat162_rn(v.x - __low2float(h01), v.y - __high2float(h01));
        __nv_bfloat162 l23 = __floats2bfloat162_rn(v.z - __low2float(h23), v.w - __high2float(h23));
        uint2 hv; hv.x = *(uint32_t*)&h01; hv.y = *(uint32_t*)&h23;
        uint2 lv; lv.x = *(uint32_t*)&l01; lv.y = *(uint32_t*)&l23;
        ((uint2*)g_Ah)[idx] = hv;
        ((uint2*)g_Al)[idx] = lv;
    } else if (idx < A_UNITS + B_UNITS) {
        int r = idx - A_UNITS;
        int j = r >> 7, q = r & 127;
        float2 v = *(const float2*)(W_in + (size_t)j * 306 + q * 2);
        __nv_bfloat16 h0 = __float2bfloat16(v.x);
        __nv_bfloat16 h1 = __float2bfloat16(v.y);
        g_Bh[(size_t)(q * 2)     * HID + j] = h0;
        g_Bh[(size_t)(q * 2 + 1) * HID + j] = h1;
        g_Bl[(size_t)(q * 2)     * HID + j] = __float2bfloat16(v.x - __bfloat162float(h0));
        g_Bl[(size_t)(q * 2 + 1) * HID + j] = __float2bfloat16(v.y - __bfloat162float(h1));
    } else if (idx < WC_OFF) {
        int r = idx - R_OFF;
        int b = r >> 6, g = r & 63;
        float val = 0.0f;
        if (g < NG && b <= NB) {
            const float delta = RBF_R / 49.0f;
            const float coeff = -0.5f / (delta * delta);
            const float binw  = RBF_R / (float)NB;
            float t = (float)b * binw - (float)g * delta;
            val = __expf(coeff * t * t);
        }
        __nv_bfloat16 h = __float2bfloat16(val);
        g_Rh[r] = h;
        g_Rl[r] = __float2bfloat16(val - __bfloat162float(h));
    } else if (idx < WQ_OFF) {
        int r = idx - WC_OFF;
        int k = r >> 10, j = r & 1023;
        float val = 0.0f;
        if (k < NG)
            val = (j < 512) ? W_in[(size_t)j * 306 + 256 + k]
                            : gate_W[(size_t)(j - 512) * NG + k];
        __nv_bfloat16 h = __float2bfloat16(val);
        g_Wch[r] = h;
        g_Wcl[r] = __float2bfloat16(val - __bfloat162float(h));
    } else if (idx < SPLIT_TOT) {
        int r = idx - WQ_OFF;   // [0, 1024)
        int lane = r & 31;
        int hpp  = (r >> 5) & 1;
        int jpos = (r >> 6) & 3;
        int jq   = r >> 8;
        int jj   = (jq * 32 + lane) * 4 + jpos;
        g_WQ[r] = make_float4(W_out[(4 * hpp + 0) * HID + jj],
                              W_out[(4 * hpp + 1) * HID + jj],
                              W_out[(4 * hpp + 2) * HID + jj],
                              W_out[(4 * hpp + 3) * HID + jj]);
    }
}

// ================= prep 1: combined WMMA (P GEMM + T GEMM w/ fused pack) ===========
#define PW_M   64
#define PW_N   128
#define PW_KT  32
#define A_LD   40
#define B_LD   264
#define EP_LD  132
#define PW_SMEM_BYTES (2 * (PW_M * A_LD * 2) + 2 * (PW_KT * B_LD * 2))   // 44032
#define PX_T   157     // grid.x: x<157 -> P GEMM, x>=157 -> T GEMM (64 tiles)

__global__ void __launch_bounds__(256, 3)
prep_gemms(const float* __restrict__ b_in) {
    extern __shared__ char smraw[];
    __nv_bfloat16* Ah = (__nv_bfloat16*)smraw;                 // [64][A_LD]
    __nv_bfloat16* Al = Ah + PW_M * A_LD;
    __nv_bfloat16* Bh = Al + PW_M * A_LD;                      // [32][B_LD]
    __nv_bfloat16* Bl = Bh + PW_KT * B_LD;
    float* Ep = (float*)smraw;                                 // overlay [64][EP_LD]

    const int tid = threadIdx.x;
    const int w   = tid >> 5;
    const int wm  = w >> 2;
    const int wn  = w & 3;
    const bool isT = (blockIdx.x >= PX_T);
    if (!isT && blockIdx.y >= 4) return;

    const int m0 = (isT ? (blockIdx.x - PX_T) : blockIdx.x) * PW_M;
    const int n0 = blockIdx.y * PW_N;
    const int KTOT    = isT ? 64 : KEMB;
    const int Astride = isT ? 64 : KEMB;
    const int Bstride = isT ? 1024 : HID;
    const __nv_bfloat16* srcAh = isT ? g_Rh  : g_Ah;
    const __nv_bfloat16* srcAl = isT ? g_Rl  : g_Al;
    const __nv_bfloat16* srcBh = isT ? g_Wch : g_Bh;
    const __nv_bfloat16* srcBl = isT ? g_Wcl : g_Bl;

    wmma::fragment<wmma::accumulator, 16, 16, 16, float> acc[2][2];
#pragma unroll
    for (int mi = 0; mi < 2; ++mi)
#pragma unroll
        for (int ni = 0; ni < 2; ++ni) wmma::fill_fragment(acc[mi][ni], 0.0f);

    for (int kt = 0; kt < KTOT; kt += PW_KT) {
        __syncthreads();
#pragma unroll
        for (int i = tid; i < 512; i += 256) {
            int half = i >> 8;
            int r = (i & 255) >> 2, q = i & 3;
            const __nv_bfloat16* src = (half ? srcAl : srcAh) + (size_t)(m0 + r) * Astride + kt;
            __nv_bfloat16* dst = (half ? Al : Ah) + r * A_LD;
            ((uint4*)dst)[q] = ((const uint4*)src)[q];
        }
#pragma unroll
        for (int i = tid; i < 1024; i += 256) {
            int half = i >> 9;
            int r = (i & 511) >> 4, q = i & 15;
            const __nv_bfloat16* src = (half ? srcBl : srcBh) + (size_t)(kt + r) * Bstride + n0;
            __nv_bfloat16* dst = (half ? Bl : Bh) + r * B_LD;
            ((uint4*)dst)[q] = ((const uint4*)src)[q];
        }
        __syncthreads();
#pragma unroll
        for (int kk = 0; kk < 2; ++kk) {
            wmma::fragment<wmma::matrix_a, 16, 16, 16, __nv_bfloat16, wmma::row_major> ah[2], al[2];
            wmma::fragment<wmma::matrix_b, 16, 16, 16, __nv_bfloat16, wmma::row_major> bh[2], bl[2];
#pragma unroll
            for (int mi = 0; mi < 2; ++mi) {
                wmma::load_matrix_sync(ah[mi], Ah + (wm * 32 + mi * 16) * A_LD + kk * 16, A_LD);
                wmma::load_matrix_sync(al[mi], Al + (wm * 32 + mi * 16) * A_LD + kk * 16, A_LD);
            }
#pragma unroll
            for (int ni = 0; ni < 2; ++ni) {
                wmma::load_matrix_sync(bh[ni], Bh + (kk * 16) * B_LD + wn * 32 + ni * 16, B_LD);
                wmma::load_matrix_sync(bl[ni], Bl + (kk * 16) * B_LD + wn * 32 + ni * 16, B_LD);
            }
#pragma unroll
            for (int mi = 0; mi < 2; ++mi)
#pragma unroll
                for (int ni = 0; ni < 2; ++ni) {
                    wmma::mma_sync(acc[mi][ni], ah[mi], bh[ni], acc[mi][ni]);
                    wmma::mma_sync(acc[mi][ni], ah[mi], bl[ni], acc[mi][ni]);
                    wmma::mma_sync(acc[mi][ni], al[mi], bh[ni], acc[mi][ni]);
                }
        }
    }
    __syncthreads();   // stage buffers dead; overlay epilogue
#pragma unroll
    for (int mi = 0; mi < 2; ++mi)
#pragma unroll
        for (int ni = 0; ni < 2; ++ni)
            wmma::store_matrix_sync(Ep + (wm * 32 + mi * 16) * EP_LD + wn * 32 + ni * 16,
                                    acc[mi][ni], EP_LD, wmma::mem_row_major);
    __syncthreads();

    if (isT) {
        // ---- fused pack: values + slopes straight to g_TPa/g_TPb (half-struct writes) ----
        float* rbfB  = Ep + PW_M * EP_LD;        // [64]
        float* browB = rbfB + 64;                // [128] boundary row m0+64
        if (tid < 64) {
            float val = 0.0f;
            if (tid < NG) {
                const float delta = RBF_R / 49.0f;
                const float coeff = -0.5f / (delta * delta);
                const float binw  = RBF_R / (float)NB;
                float t = (float)(m0 + 64) * binw - (float)tid * delta;
                val = __expf(coeff * t * t);
            }
            rbfB[tid] = val;
        }
        __syncthreads();
        if (tid < 128) {
            float s = 0.0f;
#pragma unroll
            for (int g = 0; g < NG; ++g) {
                float wv = __bfloat162float(g_Wch[(size_t)g * 1024 + n0 + tid]) +
                           __bfloat162float(g_Wcl[(size_t)g * 1024 + n0 + tid]);
                s = fmaf(rbfB[g], wv, s);
            }
            browB[tid] = s;
        }
        __syncthreads();
        const int halfoff = (n0 < 512) ? 0 : 8;
        const int gbase = (n0 & 511) >> 2;
#pragma unroll
        for (int it = tid; it < 64 * 32; it += 256) {
            int r = it >> 5, gi = it & 31;
            int b = m0 + r;                      // < NB always (64 tiles x 64 rows)
            const float* cur = Ep + r * EP_LD + gi * 4;
            const float* nxt = (r < 63) ? (Ep + (r + 1) * EP_LD + gi * 4) : (browB + gi * 4);
            float c0 = cur[0], c1 = cur[1], c2 = cur[2], c3 = cur[3];
            float x0 = nxt[0], x1 = nxt[1], x2 = nxt[2], x3 = nxt[3];
            uint2 V, S; __half2 h;
            h = __floats2half2_rn(c0, c1); V.x = *(uint32_t*)&h;
            h = __floats2half2_rn(c2, c3); V.y = *(uint32_t*)&h;
            h = __floats2half2_rn(x0 - c0, x1 - c1); S.x = *(uint32_t*)&h;
            h = __floats2half2_rn(x2 - c2, x3 - c3); S.y = *(uint32_t*)&h;
            size_t o = (size_t)b * 128 + gbase + gi;
            *(uint2*)((char*)(g_TPa + o) + halfoff) = V;
            *(uint2*)((char*)(g_TPb + o) + halfoff) = S;
        }
    } else {
#pragma unroll
        for (int i = tid; i < PW_M * PW_N; i += 256) {
            int r = i >> 7, c = i & 127;
            int pair = m0 + r;
            if (pair < NPAIR)
                g_PH[(size_t)pair * HID + n0 + c] =
                    __float2half(Ep[r * EP_LD + c] + __ldg(&b_in[n0 + c]));
        }
    }
}

// ================= main kernel (R12 winner, exact revert) =================
#define MT          256
#define BEDG        64
#define WQS_F       4096
#define RB_F        (8 * 32 * 33)
#define STG_F       (WQS_F + RB_F)
#define MAIN_SMEM_B ((STG_F + 192) * 4)

__global__ void __launch_bounds__(MT, 2)
pair_main(const int* __restrict__ anum,
          const int* __restrict__ edge_index,
          const int* __restrict__ edge_to_src,
          const float* __restrict__ dist,
          const float* __restrict__ b_out,
          float* __restrict__ out, int E) {
    extern __shared__ float sm[];
    float4* Wq4  = (float4*)sm;
    float* Rb    = sm + WQS_F;
    int*   spidx = (int*)(sm + STG_F);
    int*   sbin  = (int*)(sm + STG_F + 64);
    float* sfrac = sm + STG_F + 128;

    const int tid  = threadIdx.x;
    const int wid  = tid >> 5;
    const int lane = tid & 31;
    const int e0   = blockIdx.x * BEDG;

    for (int i = tid; i < 1024; i += MT)
        Wq4[i] = g_WQ[i];
    if (tid < BEDG) {
        int e = e0 + tid; if (e >= E) e = E - 1;
        int f = edge_to_src[e];
        int i0 = edge_index[f];
        int i1 = edge_index[E + f];
        spidx[tid] = anum[i0] + NELEM * anum[i1];
        float x = dist[e] * ((float)NB / RBF_R);
        int b = (int)x; if (b > NB - 1) b = NB - 1;
        sbin[tid] = b;
        sfrac[tid] = x - (float)b;
    }
    __syncthreads();

    const uint2* P2 = (const uint2*)g_PH;
    float* RbW = Rb + wid * (32 * 33);
    float bo8 = __ldg(&b_out[lane & 7]);

#pragma unroll 1
    for (int grp = 0; grp < 2; ++grp) {
        int pe[4], be[4]; __half2 fh2[4];
#pragma unroll
        for (int e = 0; e < 4; ++e) {
            int sl = wid * 8 + grp * 4 + e;
            pe[e] = spidx[sl]; be[e] = sbin[sl];
            fh2[e] = __float2half2_rn(sfrac[sl]);
        }
        ull po2[4][4];
#pragma unroll
        for (int a = 0; a < 4; a++)
#pragma unroll
            for (int b = 0; b < 4; b++) po2[a][b] = 0ull;

#pragma unroll
        for (int jq = 0; jq < 4; ++jq) {
            const int off = jq * 32 + lane;
            uint4 tA[4], tB[4]; uint2 ph[4];
#pragma unroll
            for (int e = 0; e < 4; ++e) {
                size_t tr = (size_t)be[e] * 128 + off;
                tA[e] = __ldg(g_TPa + tr);
                tB[e] = __ldg(g_TPb + tr);
                ph[e] = __ldg(P2 + (size_t)pe[e] * 128 + off);
            }
            ull h[4][4];
#pragma unroll
            for (int e = 0; e < 4; ++e) {
                __half2 f2 = fh2[e];
                __half2 t1a = __hfma2(f2, *(const __half2*)&tB[e].x, *(const __half2*)&tA[e].x);
                __half2 t1b = __hfma2(f2, *(const __half2*)&tB[e].y, *(const __half2*)&tA[e].y);
                __half2 g2a = __hfma2(f2, *(const __half2*)&tB[e].z, *(const __half2*)&tA[e].z);
                __half2 g2b = __hfma2(f2, *(const __half2*)&tB[e].w, *(const __half2*)&tA[e].w);
                __half2 pa  = __hadd2(*(const __half2*)&ph[e].x, t1a);
                __half2 pb  = __hadd2(*(const __half2*)&ph[e].y, t1b);
                float2 p01 = __half22float2(pa);
                float2 p23 = __half22float2(pb);
                float2 g01 = __half22float2(g2a);
                float2 g23 = __half22float2(g2b);
                float q0 = 1.0f + __expf(-p01.x);
                float q1 = 1.0f + __expf(-p01.y);
                float q2 = 1.0f + __expf(-p23.x);
                float q3 = 1.0f + __expf(-p23.y);
                float q01 = q0 * q1, q23 = q2 * q3;
                float rall = rcpa(q01 * q23);
                float r01 = rall * q23, r23 = rall * q01;
                float hv0 = p01.x * g01.x * (r01 * q1);
                float hv1 = p01.y * g01.y * (r01 * q0);
                float hv2 = p23.x * g23.x * (r23 * q3);
                float hv3 = p23.y * g23.y * (r23 * q2);
                h[e][0] = pack2(hv0, hv0); h[e][1] = pack2(hv1, hv1);
                h[e][2] = pack2(hv2, hv2); h[e][3] = pack2(hv3, hv3);
            }
#pragma unroll
            for (int jpos = 0; jpos < 4; ++jpos) {
#pragma unroll
                for (int hpp = 0; hpp < 2; ++hpp) {
                    float4 wv = Wq4[((jq * 4 + jpos) * 2 + hpp) * 32 + lane];
                    ull w01 = ((const ull*)&wv)[0];
                    ull w23 = ((const ull*)&wv)[1];
#pragma unroll
                    for (int e = 0; e < 4; ++e) {
                        fma2(po2[e][2 * hpp],     w01, h[e][jpos]);
                        fma2(po2[e][2 * hpp + 1], w23, h[e][jpos]);
                    }
                }
            }
        }

#pragma unroll
        for (int e4 = 0; e4 < 4; ++e4)
#pragma unroll
            for (int hp = 0; hp < 4; ++hp) {
                float2 v = unpack2(po2[e4][hp]);
                RbW[lane * 33 + e4 * 8 + 2 * hp]     = v.x;
                RbW[lane * 33 + e4 * 8 + 2 * hp + 1] = v.y;
            }
        __syncwarp();
        float s = bo8;
#pragma unroll
        for (int l = 0; l < 32; ++l) s += RbW[l * 33 + lane];
        int e4 = lane >> 3, h = lane & 7;
        int ge = e0 + wid * 8 + grp * 4 + e4;
        if (ge < E) out[(size_t)h * E + ge] = s;
        __syncwarp();
    }
}

// ================= launch =================
extern "C" void kernel_launch(void* const* d_in, const int* in_sizes, int n_in,
                              void* d_out, int out_size) {
    const int*   anum        = (const int*)d_in[0];
    const int*   edge_index  = (const int*)d_in[1];
    const int*   edge_to_src = (const int*)d_in[2];
    const float* dist        = (const float*)d_in[3];
    const float* emb_table   = (const float*)d_in[4];
    const float* gate_W      = (const float*)d_in[5];
    const float* W_in        = (const float*)d_in[6];
    const float* b_in        = (const float*)d_in[7];
    const float* W_out       = (const float*)d_in[8];
    const float* b_out       = (const float*)d_in[9];
    float* out = (float*)d_out;
    const int E = in_sizes[2];

    prep_stage0<<<(SPLIT_TOT + 255) / 256, 256>>>(emb_table, W_in, gate_W, W_out);

    {
        dim3 grid(PX_T + NB / PW_M, 8);   // (157+64, 8)
        cudaFuncSetAttribute(prep_gemms, cudaFuncAttributeMaxDynamicSharedMemorySize, PW_SMEM_BYTES);
        prep_gemms<<<grid, 256, PW_SMEM_BYTES>>>(b_in);
    }

    cudaFuncSetAttribute(pair_main, cudaFuncAttributeMaxDynamicSharedMemorySize, MAIN_SMEM_B);
    pair_main<<<(E + BEDG - 1) / BEDG, MT, MAIN_SMEM_B>>>(
        anum, edge_index, edge_to_src, dist, b_out, out, E);
}